// round 12
// baseline (speedup 1.0000x reference)
#include <cuda_runtime.h>
#include <math.h>

#define B_   16
#define C_   384
#define CH_  64
#define CF_  193
#define KB_  224     // padded bin count for irfft loop (7*32)
#define HW_  16384   // 128*128
#define POOLB (B_ * C_)   // 6144
#define SIDEB 20          // 12 weight compaction + 8 Ws prefetch
#define CLS  8            // cluster size (blocks per batch)

__device__ float g_y0[B_ * C_];          // pooled means
__device__ float g_rRe[B_ * CF_];        // spectral re
__device__ float g_rIm[B_ * CF_];        // spectral im
__device__ float g_W1c [CH_ * C_];       // W1 center taps   [j][n]
__device__ float g_W2cT[CH_ * C_];       // W2 center taps^T [j][c]
__device__ float g_sink[16];             // prefetch sink (never read)

// ---------------------------------------------------------------------------
// Kernel 1: global average pool (blocks 0..6143) + 20 side blocks:
// weight compaction (12), Ws1/Ws2 L2 prefetch (8).
// ---------------------------------------------------------------------------
__global__ __launch_bounds__(256) void pool_kernel(
    const float* __restrict__ x,
    const float* __restrict__ W1, const float* __restrict__ W2,
    const float* __restrict__ Ws1, const float* __restrict__ Ws2)
{
    const int bid = blockIdx.x;
    const int t   = threadIdx.x;

    if (bid >= POOLB) {
        const int s = bid - POOLB;                      // 0..19
        if (s < 6) {
            for (int e = s * 4096 + t; e < (s + 1) * 4096; e += 256) {
                int j = e / C_, n = e - j * C_;
                g_W1c[e] = W1[j * (C_ * 9) + n * 9 + 4];
            }
        } else if (s < 12) {
            for (int e = (s - 6) * 4096 + t; e < (s - 5) * 4096; e += 256) {
                int j = e / C_, c = e - j * C_;
                g_W2cT[e] = W2[c * (CH_ * 9) + j * 9 + 4];
            }
        } else {                                        // Ws1/Ws2 L2 prefetch
            const int g = s - 12;                       // 0..7
            const float* src = (g < 4) ? Ws1 : Ws2;
            const int NT = CF_ * C_;
            const int gg = g & 3;
            const int lo = (NT * gg) / 4, hi = (NT * (gg + 1)) / 4;
            float acc = 0.f;
            for (int e = lo + t; e < hi; e += 256) acc += __ldcg(src + e);
#pragma unroll
            for (int o = 16; o > 0; o >>= 1) acc += __shfl_down_sync(0xffffffffu, acc, o);
            if (t == 0 && acc == 1e38f) g_sink[g] = acc;   // never true; keeps loads
        }
        return;
    }

    const float4* __restrict__ p =
        reinterpret_cast<const float4*>(x + (size_t)bid * HW_);
    float s = 0.f;
#pragma unroll
    for (int i = 0; i < 16; ++i) {
        float4 v = __ldcs(p + t + 256 * i);
        s += (v.x + v.y) + (v.z + v.w);
    }
#pragma unroll
    for (int o = 16; o > 0; o >>= 1) s += __shfl_down_sync(0xffffffffu, s, o);
    __shared__ float ws[8];
    if ((t & 31) == 0) ws[t >> 5] = s;
    __syncthreads();
    if (t < 8) {
        s = ws[t];
#pragma unroll
        for (int o = 4; o > 0; o >>= 1) s += __shfl_down_sync(0xffu, s, o);
        if (t == 0) g_y0[bid] = s * (1.f / (float)HW_);
    }
}

// ---------------------------------------------------------------------------
// Kernel 2: whole tail, one launch. 16 clusters of 8 blocks (128 x 512).
// Base twiddle table lives in shared; all DFT factors via (k*n)%384 lookup.
// Cluster = one batch:
//   phase 0: build cT/sT (384 sincosf)
//   phase 1: every rank computes h -> y in shared (redundant)
//   phase 2: rank r computes bins [25r, ...) -> g_rRe/Im; fence
//   --- barrier.cluster ---
//   phase 3: load all bins (weight-folded) to smem; rank r computes
//            outputs [48r, 48r+48)
// ---------------------------------------------------------------------------
__global__ __launch_bounds__(512) __cluster_dims__(CLS, 1, 1)
void k_tail(
    const float* __restrict__ b1, const float* __restrict__ b2,
    const float* __restrict__ Ws1, const float* __restrict__ bs1,
    const float* __restrict__ Ws2, const float* __restrict__ bs2,
    float* __restrict__ out)
{
    const int b    = blockIdx.x / CLS;
    const int rank = blockIdx.x - b * CLS;     // 0..7
    const int t    = threadIdx.x;              // 0..511
    const int w    = t >> 5;                   // 0..15
    const int lane = t & 31;

    __shared__ __align__(16) float cT [C_];
    __shared__ __align__(16) float sT [C_];
    __shared__ __align__(16) float y0s[C_];
    __shared__ __align__(16) float ys [C_];
    __shared__ __align__(16) float sRe[KB_];
    __shared__ __align__(16) float sIm[KB_];
    __shared__ float hs[CH_];

    // ---- phase 0: base twiddles + load y0 ----
    if (t < C_) {
        float sv, cv;
        sincosf((float)t * (6.283185307179586f / (float)C_), &sv, &cv);
        cT[t] = cv;
        sT[t] = sv;
        y0s[t] = g_y0[b * C_ + t];
    }
    __syncthreads();

    // ---- phase 1a: h[j], warp per j (4 rounds) ----
    const float4* __restrict__ y04 = reinterpret_cast<const float4*>(y0s);
#pragma unroll
    for (int r = 0; r < 4; ++r) {
        const int j = w + 16 * r;
        const float4* __restrict__ wr = reinterpret_cast<const float4*>(g_W1c + j * C_);
        float acc = 0.f;
#pragma unroll
        for (int i = 0; i < 3; ++i) {
            float4 a = y04[lane * 3 + i];
            float4 ww = wr[lane * 3 + i];
            acc += a.x * ww.x + a.y * ww.y + a.z * ww.z + a.w * ww.w;
        }
#pragma unroll
        for (int o = 16; o > 0; o >>= 1) acc += __shfl_down_sync(0xffffffffu, acc, o);
        if (lane == 0) hs[j] = fmaxf(acc + b1[j], 0.f);
    }
    __syncthreads();

    // ---- phase 1b: y[c], thread per c ----
    if (t < C_) {
        float acc = b2[t];
#pragma unroll
        for (int j = 0; j < CH_; ++j)
            acc += hs[j] * g_W2cT[j * C_ + t];
        ys[t] = 1.f / (1.f + expf(-acc));
    }
    __syncthreads();

    // ---- phase 2: bins [25*rank ..), warp per bin, smem twiddle lookup ----
    {
        const int base = rank * 25;
        const int cnt  = (base + 25 <= CF_) ? 25 : (CF_ - base);  // rank7: 18
        for (int kk = w; kk < cnt; kk += 16) {
            const int k = base + kk;
            const float* __restrict__ u = Ws1 + k * C_;
            const float* __restrict__ v = Ws2 + k * C_;
            float re = 0.f, im = 0.f, a1 = 0.f, a2 = 0.f;
#pragma unroll
            for (int i = 0; i < 12; ++i) {
                const int n  = lane + 32 * i;
                const float yv = ys[n];
                const int m  = (k * n) % C_;
                re += yv * cT[m];
                im -= yv * sT[m];
                a1 += yv * u[n];
                a2 += yv * v[n];
            }
#pragma unroll
            for (int o = 16; o > 0; o >>= 1) {
                re += __shfl_down_sync(0xffffffffu, re, o);
                im += __shfl_down_sync(0xffffffffu, im, o);
                a1 += __shfl_down_sync(0xffffffffu, a1, o);
                a2 += __shfl_down_sync(0xffffffffu, a2, o);
            }
            if (lane == 0) {
                float s1  = fmaxf(a1 + bs1[k], 0.f);
                float s2  = fmaxf(a2 + bs2[k], 0.f);
                float amp = sqrtf(re * re + im * im) * s1;
                float ph  = atan2f(im, re) * s2;
                float sp, cp;
                sincosf(ph, &sp, &cp);
                g_rRe[b * CF_ + k] = amp * cp;
                g_rIm[b * CF_ + k] = amp * sp;
            }
        }
    }

    // make bin writes visible cluster-wide, then cluster barrier
    __threadfence();
    asm volatile("barrier.cluster.arrive.aligned;" ::: "memory");
    asm volatile("barrier.cluster.wait.aligned;" ::: "memory");

    // ---- phase 3: load bins (weight-folded, zero-padded) + irfft ----
    if (t < KB_) {
        if (t < CF_) {
            const float wgt = (t >= 1 && t <= 191) ? 2.f : 1.f;
            sRe[t] = wgt * g_rRe[b * CF_ + t];
            sIm[t] = wgt * g_rIm[b * CF_ + t];
        } else {
            sRe[t] = 0.f;
            sIm[t] = 0.f;
        }
    }
    __syncthreads();

#pragma unroll
    for (int r = 0; r < 3; ++r) {
        const int n = rank * 48 + w + 16 * r;
        float acc = 0.f;
#pragma unroll
        for (int i = 0; i < 7; ++i) {
            const int k = lane + 32 * i;        // 0..223 (zeros beyond 192)
            const int m = (k * n) % C_;
            acc += sRe[k] * cT[m] - sIm[k] * sT[m];
        }
#pragma unroll
        for (int o = 16; o > 0; o >>= 1) acc += __shfl_down_sync(0xffffffffu, acc, o);
        if (lane == 0) {
            float xr = acc * (1.f / (float)C_);
            out[b * C_ + n] = xr * ys[n];
        }
    }
}

// ---------------------------------------------------------------------------
extern "C" void kernel_launch(void* const* d_in, const int* in_sizes, int n_in,
                              void* d_out, int out_size) {
    const float* x   = (const float*)d_in[0];
    const float* W1  = (const float*)d_in[1];
    const float* b1  = (const float*)d_in[2];
    const float* W2  = (const float*)d_in[3];
    const float* b2  = (const float*)d_in[4];
    const float* Ws1 = (const float*)d_in[5];
    const float* bs1 = (const float*)d_in[6];
    const float* Ws2 = (const float*)d_in[7];
    const float* bs2 = (const float*)d_in[8];
    float* out = (float*)d_out;

    pool_kernel<<<POOLB + SIDEB, 256>>>(x, W1, W2, Ws1, Ws2);
    k_tail<<<B_ * CLS, 512>>>(b1, b2, Ws1, bs1, Ws2, bs2, out);
}